// round 6
// baseline (speedup 1.0000x reference)
#include <cuda_runtime.h>
#include <math.h>
#include <stdint.h>

// Problem constants
#define BATCH 512
#define HDIM  64
#define OBS   8
#define PRE   12
#define G3    192   // 3*H

// Scratch (device globals — no allocation allowed)
__device__ float  g_h[BATCH * HDIM];                 // GRU hidden state
// u double-buffered: [buf][(j>>3)*256 + (kt*4+tig)*8 + (j&7)] = {u[j][kt*8+tig], u[j][kt*8+tig+4]}
__device__ float2 g_u2[2][(BATCH / 8) * 32 * 8];
// hpart double-buffered: [buf][(j>>3)*256 + cp*8 + (j&7)] = {hp[j][2cp], hp[j][2cp+1]}
__device__ float2 g_hp2[2][(BATCH / 8) * 32 * 8];
__device__ float  g_pooled[2][BATCH * HDIM];         // atomic-max merge buffers (>=0)
__device__ int    g_cnt[PRE * BATCH];                // per (step, agent) arrival counters
__device__ float  g_WihT[HDIM * G3];                 // W_ih transposed [d][g]
__device__ float  g_WhhT[HDIM * G3];                 // W_hh transposed [d][g]
// B fragments: [(ct*4+ktp)*32 + lane] = {B(2ktp).x, B(2ktp).y, B(2ktp+1).x, B(2ktp+1).y}
__device__ uint4  g_B4[32 * 32];

__device__ __forceinline__ uint32_t f2tf32(float x) {
    uint32_t u;
    asm("cvt.rna.tf32.f32 %0, %1;" : "=r"(u) : "f"(x));
    return u;
}

__device__ __forceinline__ void mma_tf32(float& d0, float& d1, float& d2, float& d3,
                                         uint32_t a0, uint32_t a1, uint32_t a2, uint32_t a3,
                                         uint32_t b0, uint32_t b1) {
    asm volatile("mma.sync.aligned.m16n8k8.row.col.f32.tf32.tf32.f32 "
                 "{%0,%1,%2,%3}, {%4,%5,%6,%7}, {%8,%9}, {%0,%1,%2,%3};"
                 : "+f"(d0), "+f"(d1), "+f"(d2), "+f"(d3)
                 : "r"(a0), "r"(a1), "r"(a2), "r"(a3), "r"(b0), "r"(b1));
}

__device__ __forceinline__ float fsigmoid(float x) {
    return 1.0f / (1.0f + __expf(-x));
}
__device__ __forceinline__ float ftanh(float x) {
    return 2.0f / (1.0f + __expf(-2.0f * x)) - 1.0f;
}

// scalar index into the float2 u/hp layouts, viewed as float
__device__ __forceinline__ int u_scalar_idx(int j, int k) {
    int kt = k >> 3, tig = k & 3, s = (k >> 2) & 1;
    return (j >> 3) * 512 + (kt * 4 + tig) * 16 + (j & 7) * 2 + s;
}
__device__ __forceinline__ int hp_scalar_idx(int j, int c) {
    return (j >> 3) * 512 + (c >> 1) * 16 + (j & 7) * 2 + (c & 1);
}

// ---------------------------------------------------------------------------
// Init: copy group_track into out, build u2/hp2 (buf 0), zero GRU h, pooled
// buffers and counters, transpose W_ih / W_hh, precompute B fragments.
// Grid: BATCH + G3 + 32 blocks x 64 threads.
// ---------------------------------------------------------------------------
__global__ void init_kernel(const float* __restrict__ hidden,
                            const float* __restrict__ gt,
                            const float* __restrict__ W_ih,
                            const float* __restrict__ W_hh,
                            const float* __restrict__ W_rel,
                            const float* __restrict__ W_pool,
                            const float* __restrict__ b_pool,
                            float* __restrict__ out)
{
    int bid = blockIdx.x;
    int c = threadIdx.x;
    if (bid < BATCH) {
        int i = bid;
        // copy observed track: out[i, 0:8, :]
        if (c < 2 * OBS) out[i * 2 * (OBS + PRE) + c] = gt[i * 2 * OBS + c];
        // u (buf 0) from last observed position
        float px = gt[i * 2 * OBS + 2 * (OBS - 1) + 0];
        float py = gt[i * 2 * OBS + 2 * (OBS - 1) + 1];
        ((float*)g_u2[0])[u_scalar_idx(i, c)] = px * W_rel[c] + py * W_rel[HDIM + c];
        // hp (buf 0) from hidden_state
        float acc = b_pool[c];
        #pragma unroll 8
        for (int d = 0; d < HDIM; ++d)
            acc += hidden[i * HDIM + d] * W_pool[(HDIM + d) * HDIM + c];
        ((float*)g_hp2[0])[hp_scalar_idx(i, c)] = acc;
        g_h[i * HDIM + c] = 0.0f;
        // zero pooled merge buffers + counters (graph-replay safe)
        g_pooled[0][i * HDIM + c] = 0.0f;
        g_pooled[1][i * HDIM + c] = 0.0f;
        if (c < PRE) g_cnt[c * BATCH + i] = 0;
    } else if (bid < BATCH + G3) {
        int g = bid - BATCH;   // 0..191
        int d = c;             // 0..63
        g_WihT[d * G3 + g] = W_ih[g * HDIM + d];
        g_WhhT[d * G3 + g] = W_hh[g * HDIM + d];
    } else if (c < 32) {
        // B fragment precompute for one (ct, ktp): covers kt = 2ktp, 2ktp+1
        int q = bid - (BATCH + G3);   // 0..31
        int ktp = q & 3, ct = q >> 2;
        int tig = c & 3, gid = c >> 2;
        int cc = ct * 8 + gid;
        int ka = (2 * ktp) * 8 + tig;
        int kb = (2 * ktp + 1) * 8 + tig;
        uint32_t b0 = f2tf32(W_pool[ka * HDIM + cc]);
        uint32_t b1 = f2tf32(W_pool[(ka + 4) * HDIM + cc]);
        uint32_t b2 = f2tf32(W_pool[kb * HDIM + cc]);
        uint32_t b3 = f2tf32(W_pool[(kb + 4) * HDIM + cc]);
        g_B4[q * 32 + c] = make_uint4(b0, b1, b2, b3);
    }
}

// ---------------------------------------------------------------------------
// Fused step, wide grid: block = (agent i, j-quarter q). Each block spools 128
// j (4 warps x 32 j), merges via atomicMax (exact: pooled >= 0), and the LAST
// arriving block per agent runs the update tail (pos/out/emb/GRU/u/hp).
// Grid: 2048 blocks x 128 threads.
// ---------------------------------------------------------------------------
__global__ void __launch_bounds__(128, 4) step_kernel(
    const float* __restrict__ b_rel,
    const float* __restrict__ W_emb, const float* __restrict__ b_emb,
    const float* __restrict__ b_ih,  const float* __restrict__ b_hh,
    const float* __restrict__ W_pos, const float* __restrict__ b_pos,
    const float* __restrict__ W_rel, const float* __restrict__ W_pool,
    const float* __restrict__ b_pool, float* __restrict__ out, int step)
{
    __shared__ float ar_s[HDIM];      // b_rel[k] - u_i[k]
    __shared__ float red_s[4][HDIM];  // cross-warp max reduction
    __shared__ int   last_s;
    __shared__ float pos_s[2];
    __shared__ float emb_s[HDIM];
    __shared__ float hv_s[HDIM];
    __shared__ float hn_s[HDIM];

    int buf  = step & 1;
    int nbuf = buf ^ 1;
    const float2* __restrict__ u2r  = g_u2[buf];
    const float2* __restrict__ hp2r = g_hp2[buf];

    int i = blockIdx.x >> 2;
    int q = blockIdx.x & 3;
    int t = threadIdx.x;
    int w = t >> 5, l = t & 31;
    int gid = l >> 2, tig = l & 3;

    if (t < HDIM)
        ar_s[t] = b_rel[t] - ((const float*)u2r)[u_scalar_idx(i, t)];
    __syncthreads();

    int jb = q * 128 + w * 32;
    int rb = (jb >> 3) * 256;         // float2 row-block base (8 rows per 256)
    int r1 = rb + 512;                // second jtile (rows +16)

    // A fragments: e = relu(u_j + ar), tf32, for 2 jtiles x 8 ktiles (batched LDG)
    uint32_t afr[2][8][4];
    #pragma unroll
    for (int jt = 0; jt < 2; ++jt) {
        int r0 = rb + jt * 512;
        #pragma unroll
        for (int kt = 0; kt < 8; ++kt) {
            int k0 = kt * 8 + tig;
            float arx = ar_s[k0], ary = ar_s[k0 + 4];
            float2 v0 = u2r[r0 + (kt * 4 + tig) * 8 + gid];
            float2 v1 = u2r[r0 + 256 + (kt * 4 + tig) * 8 + gid];
            afr[jt][kt][0] = f2tf32(fmaxf(v0.x + arx, 0.0f));
            afr[jt][kt][1] = f2tf32(fmaxf(v1.x + arx, 0.0f));
            afr[jt][kt][2] = f2tf32(fmaxf(v0.y + ary, 0.0f));
            afr[jt][kt][3] = f2tf32(fmaxf(v1.y + ary, 0.0f));
        }
    }

    float mx[8][2];
    #pragma unroll
    for (int ct = 0; ct < 8; ++ct) { mx[ct][0] = 0.0f; mx[ct][1] = 0.0f; }  // relu => max>=0

    #pragma unroll
    for (int ct = 0; ct < 8; ++ct) {
        // C init = hpart fragments
        float2 c00 = hp2r[rb + (ct * 4 + tig) * 8 + gid];
        float2 c01 = hp2r[rb + 256 + (ct * 4 + tig) * 8 + gid];
        float2 c10 = hp2r[r1 + (ct * 4 + tig) * 8 + gid];
        float2 c11 = hp2r[r1 + 256 + (ct * 4 + tig) * 8 + gid];
        float d[2][4] = {{c00.x, c00.y, c01.x, c01.y},
                         {c10.x, c10.y, c11.x, c11.y}};
        #pragma unroll
        for (int ktp = 0; ktp < 4; ++ktp) {
            uint4 B = g_B4[(ct * 4 + ktp) * 32 + l];
            mma_tf32(d[0][0], d[0][1], d[0][2], d[0][3],
                     afr[0][2 * ktp][0], afr[0][2 * ktp][1], afr[0][2 * ktp][2], afr[0][2 * ktp][3],
                     B.x, B.y);
            mma_tf32(d[0][0], d[0][1], d[0][2], d[0][3],
                     afr[0][2 * ktp + 1][0], afr[0][2 * ktp + 1][1], afr[0][2 * ktp + 1][2], afr[0][2 * ktp + 1][3],
                     B.z, B.w);
            mma_tf32(d[1][0], d[1][1], d[1][2], d[1][3],
                     afr[1][2 * ktp][0], afr[1][2 * ktp][1], afr[1][2 * ktp][2], afr[1][2 * ktp][3],
                     B.x, B.y);
            mma_tf32(d[1][0], d[1][1], d[1][2], d[1][3],
                     afr[1][2 * ktp + 1][0], afr[1][2 * ktp + 1][1], afr[1][2 * ktp + 1][2], afr[1][2 * ktp + 1][3],
                     B.z, B.w);
        }
        mx[ct][0] = fmaxf(fmaxf(d[0][0], d[0][2]), fmaxf(d[1][0], d[1][2]));
        mx[ct][1] = fmaxf(fmaxf(d[0][1], d[0][3]), fmaxf(d[1][1], d[1][3]));
    }

    // Reduce across lane groups (gid), write per-warp result
    #pragma unroll
    for (int ct = 0; ct < 8; ++ct) {
        #pragma unroll
        for (int pp = 0; pp < 2; ++pp) {
            float v = fmaxf(mx[ct][pp], 0.0f);
            v = fmaxf(v, __shfl_xor_sync(0xffffffffu, v, 4));
            v = fmaxf(v, __shfl_xor_sync(0xffffffffu, v, 8));
            v = fmaxf(v, __shfl_xor_sync(0xffffffffu, v, 16));
            if (gid == 0) red_s[w][ct * 8 + 2 * tig + pp] = v;
        }
    }
    __syncthreads();

    // Merge this block's quarter-pool via atomicMax on uint bits (values >= 0)
    if (t < HDIM) {
        float m = fmaxf(fmaxf(red_s[0][t], red_s[1][t]), fmaxf(red_s[2][t], red_s[3][t]));
        atomicMax((unsigned int*)&g_pooled[buf][i * HDIM + t], __float_as_uint(m));
    }
    __syncthreads();
    __threadfence();   // release: pooled writes visible before counter bump
    if (t == 0)
        last_s = (atomicAdd(&g_cnt[step * BATCH + i], 1) == 3);
    __syncthreads();
    if (!last_s) return;

    // ---- update tail (only the last-arriving block per agent) ----
    __threadfence();   // acquire side
    if (w == 0) {
        float p0 = __ldcg(&g_pooled[buf][i * HDIM + l]);
        float p1 = __ldcg(&g_pooled[buf][i * HDIM + l + 32]);
        float px = p0 * W_pos[l * 2 + 0] + p1 * W_pos[(l + 32) * 2 + 0];
        float py = p0 * W_pos[l * 2 + 1] + p1 * W_pos[(l + 32) * 2 + 1];
        #pragma unroll
        for (int s = 16; s; s >>= 1) {
            px += __shfl_xor_sync(0xffffffffu, px, s);
            py += __shfl_xor_sync(0xffffffffu, py, s);
        }
        if (l == 0) {
            px += b_pos[0]; py += b_pos[1];
            out[i * 2 * (OBS + PRE) + (OBS + step) * 2 + 0] = px;
            out[i * 2 * (OBS + PRE) + (OBS + step) * 2 + 1] = py;
            pos_s[0] = px; pos_s[1] = py;
        }
    }
    __syncthreads();

    float px = pos_s[0], py = pos_s[1];
    if (t < HDIM) {
        // reset pooled slot for reuse at step+2
        g_pooled[buf][i * HDIM + t] = 0.0f;
        // next-step u
        ((float*)g_u2[nbuf])[u_scalar_idx(i, t)] = px * W_rel[t] + py * W_rel[HDIM + t];
        // emb; stage h
        emb_s[t] = px * W_emb[t] + py * W_emb[HDIM + t] + b_emb[t];
        hv_s[t]  = g_h[i * HDIM + t];
    }
    __syncthreads();

    if (t < HDIM) {
        int c = t;
        float gir = b_ih[c], giz = b_ih[64 + c], gin = b_ih[128 + c];
        float ghr = b_hh[c], ghz = b_hh[64 + c], ghn = b_hh[128 + c];
        #pragma unroll 8
        for (int d = 0; d < HDIM; ++d) {
            float ed = emb_s[d], hd = hv_s[d];
            gir += ed * g_WihT[d * G3 + c];
            giz += ed * g_WihT[d * G3 + 64 + c];
            gin += ed * g_WihT[d * G3 + 128 + c];
            ghr += hd * g_WhhT[d * G3 + c];
            ghz += hd * g_WhhT[d * G3 + 64 + c];
            ghn += hd * g_WhhT[d * G3 + 128 + c];
        }
        float r = fsigmoid(gir + ghr);
        float z = fsigmoid(giz + ghz);
        float n = ftanh(gin + r * ghn);
        float hnv = (1.0f - z) * n + z * hv_s[c];
        g_h[i * HDIM + c] = hnv;
        hn_s[c] = hnv;
    }
    __syncthreads();

    if (t < HDIM) {
        int c = t;
        float hp = b_pool[c];
        #pragma unroll 8
        for (int d = 0; d < HDIM; ++d)
            hp += hn_s[d] * W_pool[(HDIM + d) * HDIM + c];
        ((float*)g_hp2[nbuf])[hp_scalar_idx(i, c)] = hp;
    }
}

// ---------------------------------------------------------------------------
extern "C" void kernel_launch(void* const* d_in, const int* in_sizes, int n_in,
                              void* d_out, int out_size)
{
    const float* hidden = (const float*)d_in[0];
    const float* gt     = (const float*)d_in[1];
    const float* W_emb  = (const float*)d_in[2];
    const float* b_emb  = (const float*)d_in[3];
    const float* W_ih   = (const float*)d_in[4];
    const float* W_hh   = (const float*)d_in[5];
    const float* b_ih   = (const float*)d_in[6];
    const float* b_hh   = (const float*)d_in[7];
    const float* W_pos  = (const float*)d_in[8];
    const float* b_pos  = (const float*)d_in[9];
    const float* W_rel  = (const float*)d_in[10];
    const float* b_rel  = (const float*)d_in[11];
    const float* W_pool = (const float*)d_in[12];
    const float* b_pool = (const float*)d_in[13];
    float* out = (float*)d_out;

    init_kernel<<<BATCH + G3 + 32, 64>>>(hidden, gt, W_ih, W_hh, W_rel, W_pool, b_pool, out);
    for (int s = 0; s < PRE; ++s) {
        step_kernel<<<4 * BATCH, 128>>>(b_rel, W_emb, b_emb, b_ih, b_hh,
                                        W_pos, b_pos, W_rel, W_pool, b_pool,
                                        out, s);
    }
}